// round 2
// baseline (speedup 1.0000x reference)
#include <cuda_runtime.h>
#include <cuda_bf16.h>

#define Sdim 2048
#define Bdim 2
#define Edim 1024
#define Hdim 16
#define Ddim 64

// scratch: static device arrays (allocation-free rule)
__device__ float g_Q[Bdim*Hdim*Sdim*Ddim];   // [B,H,S,D]
__device__ float g_K[Bdim*Hdim*Sdim*Ddim];
__device__ float g_V[Bdim*Hdim*Sdim*Ddim];
__device__ float g_ctx[Bdim*Sdim*Edim];      // [B,S,E]

typedef unsigned long long u64;

__device__ __forceinline__ u64 pk2(float x, float y){
    u64 r; asm("mov.b64 %0,{%1,%2};" : "=l"(r) : "f"(x), "f"(y)); return r;
}
__device__ __forceinline__ void upk2(u64 v, float& x, float& y){
    asm("mov.b64 {%0,%1},%2;" : "=f"(x), "=f"(y) : "l"(v));
}
__device__ __forceinline__ void fma2(u64& c, u64 a, u64 b){
    asm("fma.rn.f32x2 %0,%1,%2,%0;" : "+l"(c) : "l"(a), "l"(b));
}

// ---------------------------------------------------------------------------
// GEMM: out[m,f] = sum_e A[m,e]*W[f,e] + bias[f].  M=4096, N=E=1024, K=E.
// modes 0/1/2: A = input [S*B,E] -> scatter to g_Q/g_K/g_V as [B,H,S,D]
// mode 3:      A = g_ctx [B*S,E] -> scatter to d_out as [S,B,E]
// 128x128x8 tiles, 256 threads, 8x8 microtile, packed f32x2 accumulators.
// ---------------------------------------------------------------------------
__global__ __launch_bounds__(256)
void mha_gemm_kernel(const float* __restrict__ A, const float* __restrict__ W,
                     const float* __restrict__ bias, float* __restrict__ outp, int mode)
{
    __shared__ __align__(16) float As[8][132];
    __shared__ __align__(16) float Ws[8][132];
    if (mode == 3) A = g_ctx;
    float* Bout = (mode==0)?g_Q : (mode==1)?g_K : (mode==2)?g_V : outp;

    int tid = threadIdx.x;
    int tx = tid & 15, ty = tid >> 4;
    int m0 = blockIdx.y << 7, f0 = blockIdx.x << 7;
    int lrow = tid >> 1, kq = (tid & 1) << 2;

    const float* Ap = A + (m0 + lrow)*Edim + kq;
    const float* Wp = W + (f0 + lrow)*Edim + kq;
    float4 asg = *(const float4*)Ap;
    float4 wsg = *(const float4*)Wp;

    u64 c2[8][4];
    #pragma unroll
    for (int i=0;i<8;i++){ c2[i][0]=0; c2[i][1]=0; c2[i][2]=0; c2[i][3]=0; }

    for (int kt = 0; kt < 128; ++kt) {
        As[kq+0][lrow]=asg.x; As[kq+1][lrow]=asg.y; As[kq+2][lrow]=asg.z; As[kq+3][lrow]=asg.w;
        Ws[kq+0][lrow]=wsg.x; Ws[kq+1][lrow]=wsg.y; Ws[kq+2][lrow]=wsg.z; Ws[kq+3][lrow]=wsg.w;
        __syncthreads();
        if (kt < 127) {
            Ap += 8; Wp += 8;
            asg = *(const float4*)Ap;
            wsg = *(const float4*)Wp;
        }
        #pragma unroll
        for (int k=0;k<8;k++){
            float4 a0 = *(const float4*)&As[k][ty*4];
            float4 a1 = *(const float4*)&As[k][64+ty*4];
            u64 b0 = *(const u64*)&Ws[k][tx*4];
            u64 b1 = *(const u64*)&Ws[k][tx*4+2];
            u64 b2 = *(const u64*)&Ws[k][64+tx*4];
            u64 b3 = *(const u64*)&Ws[k][64+tx*4+2];
            u64 ad[8];
            ad[0]=pk2(a0.x,a0.x); ad[1]=pk2(a0.y,a0.y); ad[2]=pk2(a0.z,a0.z); ad[3]=pk2(a0.w,a0.w);
            ad[4]=pk2(a1.x,a1.x); ad[5]=pk2(a1.y,a1.y); ad[6]=pk2(a1.z,a1.z); ad[7]=pk2(a1.w,a1.w);
            #pragma unroll
            for (int i=0;i<8;i++){
                fma2(c2[i][0], ad[i], b0);
                fma2(c2[i][1], ad[i], b1);
                fma2(c2[i][2], ad[i], b2);
                fma2(c2[i][3], ad[i], b3);
            }
        }
        __syncthreads();
    }

    float bv[8];
    #pragma unroll
    for (int jj=0;jj<8;jj++){
        int fl = (jj<4) ? (tx*4+jj) : (64+tx*4+(jj-4));
        bv[jj] = bias[f0+fl];
    }
    #pragma unroll
    for (int i=0;i<8;i++){
        int ml = (i<4) ? (ty*4+i) : (64+ty*4+(i-4));
        int m = m0 + ml;
        float v[8];
        upk2(c2[i][0], v[0], v[1]); upk2(c2[i][1], v[2], v[3]);
        upk2(c2[i][2], v[4], v[5]); upk2(c2[i][3], v[6], v[7]);
        #pragma unroll
        for (int jj=0;jj<8;jj++) v[jj]+=bv[jj];
        float4 lo = make_float4(v[0],v[1],v[2],v[3]);
        float4 hi = make_float4(v[4],v[5],v[6],v[7]);
        if (mode < 3) {
            int s = m >> 1, b = m & 1;          // m = s*B + b
            int fA = f0 + tx*4, fB = fA + 64;
            *(float4*)&Bout[(((b*Hdim) + (fA>>6))*Sdim + s)*Ddim + (fA&63)] = lo;
            *(float4*)&Bout[(((b*Hdim) + (fB>>6))*Sdim + s)*Ddim + (fB&63)] = hi;
        } else {
            int b = m >> 11, s = m & 2047;      // m = b*S + s
            float* o = Bout + (s*Bdim + b)*Edim + f0;
            *(float4*)&o[tx*4] = lo;
            *(float4*)&o[64+tx*4] = hi;
        }
    }
}

// ---------------------------------------------------------------------------
// scores[bh,q,k] = 0.125*(Q[bh,q,:]·K[bh,k,:]) + bias[q,k]
// 128x128 tile per CTA over (q,k); depth 64 in chunks of 8.
// ---------------------------------------------------------------------------
__global__ __launch_bounds__(256)
void mha_scores_kernel(const float* __restrict__ bias, float* __restrict__ attn)
{
    __shared__ __align__(16) float Qs[8][132];
    __shared__ __align__(16) float Ks[8][132];
    int tid = threadIdx.x;
    int tx = tid & 15, ty = tid >> 4;
    int k0 = blockIdx.x << 7, q0 = blockIdx.y << 7;
    int bh = blockIdx.z;
    const float* Qg = g_Q + ((size_t)bh*Sdim + q0)*Ddim;
    const float* Kg = g_K + ((size_t)bh*Sdim + k0)*Ddim;
    int lrow = tid >> 1, kq = (tid & 1) << 2;

    float4 qld = *(const float4*)&Qg[lrow*Ddim + kq];
    float4 kld = *(const float4*)&Kg[lrow*Ddim + kq];

    u64 c2[8][4];
    #pragma unroll
    for (int i=0;i<8;i++){ c2[i][0]=0; c2[i][1]=0; c2[i][2]=0; c2[i][3]=0; }

    for (int kt = 0; kt < 8; ++kt) {
        Qs[kq+0][lrow]=qld.x; Qs[kq+1][lrow]=qld.y; Qs[kq+2][lrow]=qld.z; Qs[kq+3][lrow]=qld.w;
        Ks[kq+0][lrow]=kld.x; Ks[kq+1][lrow]=kld.y; Ks[kq+2][lrow]=kld.z; Ks[kq+3][lrow]=kld.w;
        __syncthreads();
        if (kt < 7) {
            qld = *(const float4*)&Qg[lrow*Ddim + (kt+1)*8 + kq];
            kld = *(const float4*)&Kg[lrow*Ddim + (kt+1)*8 + kq];
        }
        #pragma unroll
        for (int k=0;k<8;k++){
            float4 a0 = *(const float4*)&Qs[k][ty*4];
            float4 a1 = *(const float4*)&Qs[k][64+ty*4];
            u64 b0 = *(const u64*)&Ks[k][tx*4];
            u64 b1 = *(const u64*)&Ks[k][tx*4+2];
            u64 b2 = *(const u64*)&Ks[k][64+tx*4];
            u64 b3 = *(const u64*)&Ks[k][64+tx*4+2];
            u64 ad[8];
            ad[0]=pk2(a0.x,a0.x); ad[1]=pk2(a0.y,a0.y); ad[2]=pk2(a0.z,a0.z); ad[3]=pk2(a0.w,a0.w);
            ad[4]=pk2(a1.x,a1.x); ad[5]=pk2(a1.y,a1.y); ad[6]=pk2(a1.z,a1.z); ad[7]=pk2(a1.w,a1.w);
            #pragma unroll
            for (int i=0;i<8;i++){
                fma2(c2[i][0], ad[i], b0);
                fma2(c2[i][1], ad[i], b1);
                fma2(c2[i][2], ad[i], b2);
                fma2(c2[i][3], ad[i], b3);
            }
        }
        __syncthreads();
    }

    #pragma unroll
    for (int i=0;i<8;i++){
        int ml = (i<4) ? (ty*4+i) : (64+ty*4+(i-4));
        int q = q0 + ml;
        float v[8];
        upk2(c2[i][0], v[0], v[1]); upk2(c2[i][1], v[2], v[3]);
        upk2(c2[i][2], v[4], v[5]); upk2(c2[i][3], v[6], v[7]);
        float4 bl = *(const float4*)&bias[(size_t)q*Sdim + k0 + tx*4];
        float4 bh4= *(const float4*)&bias[(size_t)q*Sdim + k0 + 64 + tx*4];
        float4 lo = make_float4(v[0]*0.125f+bl.x, v[1]*0.125f+bl.y,
                                v[2]*0.125f+bl.z, v[3]*0.125f+bl.w);
        float4 hi = make_float4(v[4]*0.125f+bh4.x, v[5]*0.125f+bh4.y,
                                v[6]*0.125f+bh4.z, v[7]*0.125f+bh4.w);
        float* row = attn + ((size_t)bh*Sdim + q)*Sdim;
        *(float4*)&row[k0 + tx*4] = lo;
        *(float4*)&row[k0 + 64 + tx*4] = hi;
    }
}

// ---------------------------------------------------------------------------
// Row softmax in place. One CTA per row (B*H*S rows, 2048 cols, 8/thread).
// ---------------------------------------------------------------------------
__global__ __launch_bounds__(256)
void mha_softmax_kernel(float* __restrict__ attn)
{
    __shared__ float red[8];
    size_t row = blockIdx.x;
    float* p = attn + row*(size_t)Sdim;
    int tid = threadIdx.x;
    int lane = tid & 31, warp = tid >> 5;
    float4 x0 = *(const float4*)&p[tid*8];
    float4 x1 = *(const float4*)&p[tid*8+4];
    float m = fmaxf(fmaxf(fmaxf(x0.x,x0.y),fmaxf(x0.z,x0.w)),
                    fmaxf(fmaxf(x1.x,x1.y),fmaxf(x1.z,x1.w)));
    #pragma unroll
    for (int o=16;o>0;o>>=1) m = fmaxf(m, __shfl_xor_sync(0xffffffffu, m, o));
    if (lane==0) red[warp] = m;
    __syncthreads();
    m = red[0];
    #pragma unroll
    for (int i=1;i<8;i++) m = fmaxf(m, red[i]);
    __syncthreads();

    float e[8];
    e[0]=__expf(x0.x-m); e[1]=__expf(x0.y-m); e[2]=__expf(x0.z-m); e[3]=__expf(x0.w-m);
    e[4]=__expf(x1.x-m); e[5]=__expf(x1.y-m); e[6]=__expf(x1.z-m); e[7]=__expf(x1.w-m);
    float s = e[0]+e[1]+e[2]+e[3]+e[4]+e[5]+e[6]+e[7];
    #pragma unroll
    for (int o=16;o>0;o>>=1) s += __shfl_xor_sync(0xffffffffu, s, o);
    if (lane==0) red[warp] = s;
    __syncthreads();
    s = red[0]+red[1]+red[2]+red[3]+red[4]+red[5]+red[6]+red[7];
    float inv = 1.0f / s;
    float4 o0 = make_float4(e[0]*inv, e[1]*inv, e[2]*inv, e[3]*inv);
    float4 o1 = make_float4(e[4]*inv, e[5]*inv, e[6]*inv, e[7]*inv);
    *(float4*)&p[tid*8] = o0;
    *(float4*)&p[tid*8+4] = o1;
}

// ---------------------------------------------------------------------------
// context: ctx[b,s,h*64+d] = sum_k attn[bh,s,k] * V[bh,k,d]
// 128(q) x 64(d) tile per CTA, depth 2048 in chunks of 8. 8x4 microtile.
// ---------------------------------------------------------------------------
__global__ __launch_bounds__(256)
void mha_context_kernel(const float* __restrict__ attn)
{
    __shared__ __align__(16) float As[8][132];
    __shared__ __align__(16) float Vs[8][68];
    int tid = threadIdx.x;
    int tx = tid & 15, ty = tid >> 4;
    int q0 = blockIdx.x << 7;
    int bh = blockIdx.y, b = bh >> 4, h = bh & 15;
    const float* Ag = attn + ((size_t)bh*Sdim + q0)*Sdim;
    const float* Vg = g_V + (size_t)bh*Sdim*Ddim;
    int lrow = tid >> 1, kq = (tid & 1) << 2;

    u64 c2[8][2];
    #pragma unroll
    for (int i=0;i<8;i++){ c2[i][0]=0; c2[i][1]=0; }

    for (int kt = 0; kt < 256; ++kt) {
        int kbase = kt*8;
        float4 a = *(const float4*)&Ag[(size_t)lrow*Sdim + kbase + kq];
        float4 vv = make_float4(0.f,0.f,0.f,0.f);
        if (tid < 128)
            vv = *(const float4*)&Vg[(size_t)(kbase + (tid>>4))*Ddim + (tid&15)*4];
        __syncthreads();
        As[kq+0][lrow]=a.x; As[kq+1][lrow]=a.y; As[kq+2][lrow]=a.z; As[kq+3][lrow]=a.w;
        if (tid < 128) {
            int kk = tid>>4, d4 = (tid&15)*4;
            Vs[kk][d4+0]=vv.x; Vs[kk][d4+1]=vv.y; Vs[kk][d4+2]=vv.z; Vs[kk][d4+3]=vv.w;
        }
        __syncthreads();
        #pragma unroll
        for (int k=0;k<8;k++){
            float4 a0 = *(const float4*)&As[k][ty*4];
            float4 a1 = *(const float4*)&As[k][64+ty*4];
            u64 b0 = *(const u64*)&Vs[k][tx*4];
            u64 b1 = *(const u64*)&Vs[k][tx*4+2];
            u64 ad[8];
            ad[0]=pk2(a0.x,a0.x); ad[1]=pk2(a0.y,a0.y); ad[2]=pk2(a0.z,a0.z); ad[3]=pk2(a0.w,a0.w);
            ad[4]=pk2(a1.x,a1.x); ad[5]=pk2(a1.y,a1.y); ad[6]=pk2(a1.z,a1.z); ad[7]=pk2(a1.w,a1.w);
            #pragma unroll
            for (int i=0;i<8;i++){
                fma2(c2[i][0], ad[i], b0);
                fma2(c2[i][1], ad[i], b1);
            }
        }
    }

    #pragma unroll
    for (int i=0;i<8;i++){
        int ml = (i<4) ? (ty*4+i) : (64+ty*4+(i-4));
        int s = q0 + ml;
        float v[4];
        upk2(c2[i][0], v[0], v[1]); upk2(c2[i][1], v[2], v[3]);
        float4 o = make_float4(v[0],v[1],v[2],v[3]);
        *(float4*)&g_ctx[((size_t)b*Sdim + s)*Edim + h*64 + tx*4] = o;
    }
}

extern "C" void kernel_launch(void* const* d_in, const int* in_sizes, int n_in,
                              void* d_out, int out_size) {
    const float* query = (const float*)d_in[0];
    const float* key_  = (const float*)d_in[1];
    const float* value = (const float*)d_in[2];
    const float* Wq = (const float*)d_in[3];
    const float* bq = (const float*)d_in[4];
    const float* Wk = (const float*)d_in[5];
    const float* bk = (const float*)d_in[6];
    const float* Wv = (const float*)d_in[7];
    const float* bv = (const float*)d_in[8];
    const float* Wo = (const float*)d_in[9];
    const float* bo = (const float*)d_in[10];
    const float* bias_matrix = (const float*)d_in[11];

    float* out  = (float*)d_out;                              // [S,B,E]
    float* attn = out + (size_t)Sdim*Bdim*Edim;               // [B,H,S,S]

    dim3 gproj(Edim/128, (Sdim*Bdim)/128);                    // (8, 32)
    mha_gemm_kernel<<<gproj, 256>>>(query, Wq, bq, nullptr, 0);
    mha_gemm_kernel<<<gproj, 256>>>(key_,  Wk, bk, nullptr, 1);
    mha_gemm_kernel<<<gproj, 256>>>(value, Wv, bv, nullptr, 2);

    dim3 gsc(Sdim/128, Sdim/128, Bdim*Hdim);                  // (16,16,32)
    mha_scores_kernel<<<gsc, 256>>>(bias_matrix, attn);

    mha_softmax_kernel<<<Bdim*Hdim*Sdim, 256>>>(attn);

    dim3 gctx(Sdim/128, Bdim*Hdim);                           // (16,32)
    mha_context_kernel<<<gctx, 256>>>(attn);

    mha_gemm_kernel<<<gproj, 256>>>(nullptr, Wo, bo, out, 3);
}

// round 4
// speedup vs baseline: 1.6108x; 1.6108x over previous
#include <cuda_runtime.h>
#include <cuda_bf16.h>
#include <cstdint>

#define Sdim 2048
#define Bdim 2
#define Edim 1024
#define Hdim 16
#define Ddim 64
#define APAD 40   // bf16 elems per smem tile row (80B stride: conflict-free ldmatrix)

typedef uint32_t u32;

// scratch: static device arrays (allocation-free rule)
__device__ float g_Q[Bdim*Hdim*Sdim*Ddim];     // [B,H,S,D]
__device__ float g_K[Bdim*Hdim*Sdim*Ddim];     // [B,H,S,D]
__device__ float g_Vt[Bdim*Hdim*Ddim*Sdim];    // [B,H,D,S]  (transposed V)
__device__ float g_ctx[Bdim*Sdim*Edim];        // [B,S,E]

__device__ __forceinline__ u32 smem_u32(const void* p){
    u32 a;
    asm("{ .reg .u64 t; cvta.to.shared.u64 t, %1; cvt.u32.u64 %0, t; }" : "=r"(a) : "l"(p));
    return a;
}
__device__ __forceinline__ void ldsm4(u32 r[4], u32 addr){
    asm volatile("ldmatrix.sync.aligned.m8n8.x4.shared.b16 {%0,%1,%2,%3}, [%4];"
        : "=r"(r[0]),"=r"(r[1]),"=r"(r[2]),"=r"(r[3]) : "r"(addr));
}
__device__ __forceinline__ void ldsm2(u32 r[2], u32 addr){
    asm volatile("ldmatrix.sync.aligned.m8n8.x2.shared.b16 {%0,%1}, [%2];"
        : "=r"(r[0]),"=r"(r[1]) : "r"(addr));
}
__device__ __forceinline__ void mma16816(float c[4], const u32 a[4], const u32 b[2]){
    asm volatile("mma.sync.aligned.m16n8k16.row.col.f32.bf16.bf16.f32 "
        "{%0,%1,%2,%3}, {%4,%5,%6,%7}, {%8,%9}, {%0,%1,%2,%3};"
        : "+f"(c[0]),"+f"(c[1]),"+f"(c[2]),"+f"(c[3])
        : "r"(a[0]),"r"(a[1]),"r"(a[2]),"r"(a[3]), "r"(b[0]),"r"(b[1]));
}

// split fp32 pair -> hi/lo bf16x2 into padded smem tiles at element index idx (even)
__device__ __forceinline__ void split2(__nv_bfloat16* hi, __nv_bfloat16* lo, int idx, float x, float y){
    __nv_bfloat16 hx = __float2bfloat16(x), hy = __float2bfloat16(y);
    float rx = x - __bfloat162float(hx), ry = y - __bfloat162float(hy);
    *(__nv_bfloat162*)(hi+idx) = __halves2bfloat162(hx, hy);
    *(__nv_bfloat162*)(lo+idx) = __halves2bfloat162(__float2bfloat16(rx), __float2bfloat16(ry));
}

// ---------------------------------------------------------------------------
// Projection GEMM: out[m,f] = sum_e A[m,e]*W[f,e] + bias[f].  M=4096,N=1024,K=1024
// modes 0/1: scatter to g_Q/g_K [B,H,S,D]; 2: transposed into g_Vt [B,H,D,S];
// 3: A=g_ctx [B*S,E], scatter to out [S,B,E].
// 128x128 tile, K-chunks of 32. 8 warps: wm 4 x wn 2 (32x64 each).
// ---------------------------------------------------------------------------
__global__ void __launch_bounds__(256, 2)
mha_proj_mma(const float* __restrict__ A, const float* __restrict__ W,
             const float* __restrict__ bias, float* __restrict__ outp, int mode)
{
    __shared__ __align__(16) __nv_bfloat16 Ah[128*APAD], Al[128*APAD];
    __shared__ __align__(16) __nv_bfloat16 Bh[128*APAD], Bl[128*APAD];
    if (mode == 3) A = g_ctx;

    int tid = threadIdx.x, wid = tid >> 5, lane = tid & 31;
    int m0 = blockIdx.y << 7, f0 = blockIdx.x << 7;
    int wm = (wid & 3) << 5, wn = (wid >> 2) << 6;

    u32 sAh = smem_u32(Ah), sAl = smem_u32(Al), sBh = smem_u32(Bh), sBl = smem_u32(Bl);

    // ldmatrix lane address components
    int a_r = (lane & 7) + ((lane >> 3) & 1) * 8;   // row within 16
    int a_c = ((lane >> 4) & 1) * 8;                // col 0/8
    int b_r = lane & 7;
    int b_c = ((lane >> 3) & 1) * 8;

    int lrow = tid >> 1, cb0 = (tid & 1) * 16;      // gmem load: 2 thr/row, 16 floats each

    float acc[16][4];
    #pragma unroll
    for (int i = 0; i < 16; i++){ acc[i][0]=0.f; acc[i][1]=0.f; acc[i][2]=0.f; acc[i][3]=0.f; }

    const float* Ap = A + (size_t)(m0 + lrow)*Edim + cb0;
    const float* Wp = W + (size_t)(f0 + lrow)*Edim + cb0;

    for (int c = 0; c < 32; c++) {
        float4 av[4], wv[4];
        #pragma unroll
        for (int j = 0; j < 4; j++) {
            av[j] = *(const float4*)(Ap + c*32 + j*4);
            wv[j] = *(const float4*)(Wp + c*32 + j*4);
        }
        __syncthreads();
        #pragma unroll
        for (int j = 0; j < 4; j++) {
            int idx = lrow*APAD + cb0 + j*4;
            split2(Ah, Al, idx,   av[j].x, av[j].y);
            split2(Ah, Al, idx+2, av[j].z, av[j].w);
            split2(Bh, Bl, idx,   wv[j].x, wv[j].y);
            split2(Bh, Bl, idx+2, wv[j].z, wv[j].w);
        }
        __syncthreads();
        #pragma unroll
        for (int ks = 0; ks < 32; ks += 16) {
            u32 ah0[4], ah1[4], al0[4], al1[4];
            u32 aoff0 = (u32)((wm      + a_r)*APAD + ks + a_c) * 2;
            u32 aoff1 = (u32)((wm + 16 + a_r)*APAD + ks + a_c) * 2;
            ldsm4(ah0, sAh + aoff0); ldsm4(ah1, sAh + aoff1);
            ldsm4(al0, sAl + aoff0); ldsm4(al1, sAl + aoff1);
            #pragma unroll
            for (int nf = 0; nf < 8; nf++) {
                u32 boff = (u32)((wn + nf*8 + b_r)*APAD + ks + b_c) * 2;
                u32 bh[2], bl[2];
                ldsm2(bh, sBh + boff); ldsm2(bl, sBl + boff);
                mma16816(acc[nf],   ah0, bh);
                mma16816(acc[nf],   ah0, bl);
                mma16816(acc[nf],   al0, bh);
                mma16816(acc[8+nf], ah1, bh);
                mma16816(acc[8+nf], ah1, bl);
                mma16816(acc[8+nf], al1, bh);
            }
        }
    }

    // epilogue
    int gr = lane >> 2, ti = lane & 3;
    #pragma unroll
    for (int mf = 0; mf < 2; mf++) {
        #pragma unroll
        for (int nf = 0; nf < 8; nf++) {
            float* a4 = acc[mf*8 + nf];
            int f = f0 + wn + nf*8 + ti*2;
            float2 bz = *(const float2*)&bias[f];
            #pragma unroll
            for (int hh = 0; hh < 2; hh++) {
                int m = m0 + wm + mf*16 + gr + hh*8;
                float vx = a4[hh*2]   + bz.x;
                float vy = a4[hh*2+1] + bz.y;
                if (mode < 3) {
                    int s = m >> 1, b = m & 1;
                    int h = f >> 6, d = f & 63;
                    if (mode == 2) {
                        float* vt = g_Vt + ((size_t)(b*Hdim + h)*Ddim + d)*Sdim + s;
                        vt[0] = vx; vt[Sdim] = vy;
                    } else {
                        float* dst = (mode == 0) ? g_Q : g_K;
                        *(float2*)&dst[(((size_t)(b*Hdim + h))*Sdim + s)*Ddim + d] =
                            make_float2(vx, vy);
                    }
                } else {
                    int b = m >> 11, s = m & 2047;
                    *(float2*)&outp[((size_t)s*Bdim + b)*Edim + f] = make_float2(vx, vy);
                }
            }
        }
    }
}

// ---------------------------------------------------------------------------
// Scores: attn[bh,q,k] = 0.125*(Q·K) + bias[q,k].  128x128 tile, K=64 (2 chunks).
// ---------------------------------------------------------------------------
__global__ void __launch_bounds__(256, 2)
mha_scores_mma(const float* __restrict__ bias, float* __restrict__ attn)
{
    __shared__ __align__(16) __nv_bfloat16 Ah[128*APAD], Al[128*APAD];
    __shared__ __align__(16) __nv_bfloat16 Bh[128*APAD], Bl[128*APAD];

    int tid = threadIdx.x, wid = tid >> 5, lane = tid & 31;
    int k0 = blockIdx.x << 7, q0 = blockIdx.y << 7, bh = blockIdx.z;
    int wm = (wid & 3) << 5, wn = (wid >> 2) << 6;
    const float* Qg = g_Q + ((size_t)bh*Sdim + q0)*Ddim;
    const float* Kg = g_K + ((size_t)bh*Sdim + k0)*Ddim;

    u32 sAh = smem_u32(Ah), sAl = smem_u32(Al), sBh = smem_u32(Bh), sBl = smem_u32(Bl);
    int a_r = (lane & 7) + ((lane >> 3) & 1) * 8;
    int a_c = ((lane >> 4) & 1) * 8;
    int b_r = lane & 7;
    int b_c = ((lane >> 3) & 1) * 8;
    int lrow = tid >> 1, cb0 = (tid & 1) * 16;

    float acc[16][4];
    #pragma unroll
    for (int i = 0; i < 16; i++){ acc[i][0]=0.f; acc[i][1]=0.f; acc[i][2]=0.f; acc[i][3]=0.f; }

    for (int c = 0; c < 2; c++) {
        float4 qv[4], kv[4];
        #pragma unroll
        for (int j = 0; j < 4; j++) {
            qv[j] = *(const float4*)&Qg[(size_t)lrow*Ddim + c*32 + cb0 + j*4];
            kv[j] = *(const float4*)&Kg[(size_t)lrow*Ddim + c*32 + cb0 + j*4];
        }
        __syncthreads();
        #pragma unroll
        for (int j = 0; j < 4; j++) {
            int idx = lrow*APAD + cb0 + j*4;
            split2(Ah, Al, idx,   qv[j].x, qv[j].y);
            split2(Ah, Al, idx+2, qv[j].z, qv[j].w);
            split2(Bh, Bl, idx,   kv[j].x, kv[j].y);
            split2(Bh, Bl, idx+2, kv[j].z, kv[j].w);
        }
        __syncthreads();
        #pragma unroll
        for (int ks = 0; ks < 32; ks += 16) {
            u32 ah0[4], ah1[4], al0[4], al1[4];
            u32 aoff0 = (u32)((wm      + a_r)*APAD + ks + a_c) * 2;
            u32 aoff1 = (u32)((wm + 16 + a_r)*APAD + ks + a_c) * 2;
            ldsm4(ah0, sAh + aoff0); ldsm4(ah1, sAh + aoff1);
            ldsm4(al0, sAl + aoff0); ldsm4(al1, sAl + aoff1);
            #pragma unroll
            for (int nf = 0; nf < 8; nf++) {
                u32 boff = (u32)((wn + nf*8 + b_r)*APAD + ks + b_c) * 2;
                u32 bhf[2], blf[2];
                ldsm2(bhf, sBh + boff); ldsm2(blf, sBl + boff);
                mma16816(acc[nf],   ah0, bhf);
                mma16816(acc[nf],   ah0, blf);
                mma16816(acc[nf],   al0, bhf);
                mma16816(acc[8+nf], ah1, bhf);
                mma16816(acc[8+nf], ah1, blf);
                mma16816(acc[8+nf], al1, bhf);
            }
        }
    }

    int gr = lane >> 2, ti = lane & 3;
    #pragma unroll
    for (int mf = 0; mf < 2; mf++) {
        #pragma unroll
        for (int nf = 0; nf < 8; nf++) {
            float* a4 = acc[mf*8 + nf];
            int kk = k0 + wn + nf*8 + ti*2;
            #pragma unroll
            for (int hh = 0; hh < 2; hh++) {
                int q = q0 + wm + mf*16 + gr + hh*8;
                float2 bz = *(const float2*)&bias[(size_t)q*Sdim + kk];
                float2 v = make_float2(a4[hh*2]*0.125f + bz.x, a4[hh*2+1]*0.125f + bz.y);
                *(float2*)&attn[((size_t)bh*Sdim + q)*Sdim + kk] = v;
            }
        }
    }
}

// ---------------------------------------------------------------------------
// Row softmax in place (pure bandwidth).
// ---------------------------------------------------------------------------
__global__ void __launch_bounds__(256)
mha_softmax_kernel(float* __restrict__ attn)
{
    __shared__ float red[8];
    size_t rowi = blockIdx.x;
    float* p = attn + rowi*(size_t)Sdim;
    int tid = threadIdx.x, lane = tid & 31, warp = tid >> 5;
    float4 x0 = *(const float4*)&p[tid*8];
    float4 x1 = *(const float4*)&p[tid*8+4];
    float m = fmaxf(fmaxf(fmaxf(x0.x,x0.y),fmaxf(x0.z,x0.w)),
                    fmaxf(fmaxf(x1.x,x1.y),fmaxf(x1.z,x1.w)));
    #pragma unroll
    for (int o=16;o>0;o>>=1) m = fmaxf(m, __shfl_xor_sync(0xffffffffu, m, o));
    if (lane==0) red[warp] = m;
    __syncthreads();
    m = red[0];
    #pragma unroll
    for (int i=1;i<8;i++) m = fmaxf(m, red[i]);
    __syncthreads();
    float e[8];
    e[0]=__expf(x0.x-m); e[1]=__expf(x0.y-m); e[2]=__expf(x0.z-m); e[3]=__expf(x0.w-m);
    e[4]=__expf(x1.x-m); e[5]=__expf(x1.y-m); e[6]=__expf(x1.z-m); e[7]=__expf(x1.w-m);
    float s = e[0]+e[1]+e[2]+e[3]+e[4]+e[5]+e[6]+e[7];
    #pragma unroll
    for (int o=16;o>0;o>>=1) s += __shfl_xor_sync(0xffffffffu, s, o);
    if (lane==0) red[warp] = s;
    __syncthreads();
    s = red[0]+red[1]+red[2]+red[3]+red[4]+red[5]+red[6]+red[7];
    float inv = 1.0f / s;
    *(float4*)&p[tid*8]   = make_float4(e[0]*inv, e[1]*inv, e[2]*inv, e[3]*inv);
    *(float4*)&p[tid*8+4] = make_float4(e[4]*inv, e[5]*inv, e[6]*inv, e[7]*inv);
}

// ---------------------------------------------------------------------------
// Context: ctx[b,s,h*64+d] = sum_k attn[bh,s,k] * Vt[bh,d,k]
// 128(q) x 64(d) tile, K=2048 in 64 chunks of 32. 8 warps: wm 4 x wn 2 (32x32).
// ---------------------------------------------------------------------------
__global__ void __launch_bounds__(256, 2)
mha_ctx_mma(const float* __restrict__ attn)
{
    __shared__ __align__(16) __nv_bfloat16 Ah[128*APAD], Al[128*APAD];
    __shared__ __align__(16) __nv_bfloat16 Vh[64*APAD],  Vl[64*APAD];

    int tid = threadIdx.x, wid = tid >> 5, lane = tid & 31;
    int q0 = blockIdx.x << 7, bh = blockIdx.y;
    int b = bh >> 4, h = bh & 15;
    int wm = (wid & 3) << 5, wn = (wid >> 2) << 5;
    const float* Ag = attn + ((size_t)bh*Sdim + q0)*Sdim;
    const float* Vg = g_Vt + (size_t)bh*Ddim*Sdim;

    u32 sAh = smem_u32(Ah), sAl = smem_u32(Al), sVh = smem_u32(Vh), sVl = smem_u32(Vl);
    int a_r = (lane & 7) + ((lane >> 3) & 1) * 8;
    int a_c = ((lane >> 4) & 1) * 8;
    int b_r = lane & 7;
    int b_c = ((lane >> 3) & 1) * 8;

    int lrow = tid >> 1, cb0 = (tid & 1) * 16;   // attn tile loads
    int vrow = tid >> 2, vb0 = (tid & 3) * 8;    // V tile loads

    float acc[8][4];
    #pragma unroll
    for (int i = 0; i < 8; i++){ acc[i][0]=0.f; acc[i][1]=0.f; acc[i][2]=0.f; acc[i][3]=0.f; }

    for (int c = 0; c < 64; c++) {
        float4 av[4], vv[2];
        #pragma unroll
        for (int j = 0; j < 4; j++)
            av[j] = *(const float4*)&Ag[(size_t)lrow*Sdim + c*32 + cb0 + j*4];
        #pragma unroll
        for (int j = 0; j < 2; j++)
            vv[j] = *(const float4*)&Vg[(size_t)vrow*Sdim + c*32 + vb0 + j*4];
        __syncthreads();
        #pragma unroll
        for (int j = 0; j < 4; j++) {
            int idx = lrow*APAD + cb0 + j*4;
            split2(Ah, Al, idx,   av[j].x, av[j].y);
            split2(Ah, Al, idx+2, av[j].z, av[j].w);
        }
        #pragma unroll
        for (int j = 0; j < 2; j++) {
            int idx = vrow*APAD + vb0 + j*4;
            split2(Vh, Vl, idx,   vv[j].x, vv[j].y);
            split2(Vh, Vl, idx+2, vv[j].z, vv[j].w);
        }
        __syncthreads();
        #pragma unroll
        for (int ks = 0; ks < 32; ks += 16) {
            u32 ah0[4], ah1[4], al0[4], al1[4];
            u32 aoff0 = (u32)((wm      + a_r)*APAD + ks + a_c) * 2;
            u32 aoff1 = (u32)((wm + 16 + a_r)*APAD + ks + a_c) * 2;
            ldsm4(ah0, sAh + aoff0); ldsm4(ah1, sAh + aoff1);
            ldsm4(al0, sAl + aoff0); ldsm4(al1, sAl + aoff1);
            #pragma unroll
            for (int nf = 0; nf < 4; nf++) {
                u32 boff = (u32)((wn + nf*8 + b_r)*APAD + ks + b_c) * 2;
                u32 bhf[2], blf[2];
                ldsm2(bhf, sVh + boff); ldsm2(blf, sVl + boff);
                mma16816(acc[nf],   ah0, bhf);
                mma16816(acc[nf],   ah0, blf);
                mma16816(acc[nf],   al0, bhf);
                mma16816(acc[4+nf], ah1, bhf);
                mma16816(acc[4+nf], ah1, blf);
                mma16816(acc[4+nf], al1, bhf);
            }
        }
    }

    int gr = lane >> 2, ti = lane & 3;
    #pragma unroll
    for (int mf = 0; mf < 2; mf++) {
        #pragma unroll
        for (int nf = 0; nf < 4; nf++) {
            float* a4 = acc[mf*4 + nf];
            int d = wn + nf*8 + ti*2;
            #pragma unroll
            for (int hh = 0; hh < 2; hh++) {
                int s = q0 + wm + mf*16 + gr + hh*8;
                *(float2*)&g_ctx[((size_t)b*Sdim + s)*Edim + h*64 + d] =
                    make_float2(a4[hh*2], a4[hh*2+1]);
            }
        }
    }
}

extern "C" void kernel_launch(void* const* d_in, const int* in_sizes, int n_in,
                              void* d_out, int out_size) {
    const float* query = (const float*)d_in[0];
    const float* key_  = (const float*)d_in[1];
    const float* value = (const float*)d_in[2];
    const float* Wq = (const float*)d_in[3];
    const float* bq = (const float*)d_in[4];
    const float* Wk = (const float*)d_in[5];
    const float* bk = (const float*)d_in[6];
    const float* Wv = (const float*)d_in[7];
    const float* bv = (const float*)d_in[8];
    const float* Wo = (const float*)d_in[9];
    const float* bo = (const float*)d_in[10];
    const float* bias_matrix = (const float*)d_in[11];

    float* out  = (float*)d_out;                    // [S,B,E]
    float* attn = out + (size_t)Sdim*Bdim*Edim;     // [B,H,S,S]

    dim3 gproj(Edim/128, (Sdim*Bdim)/128);          // (8, 32)
    mha_proj_mma<<<gproj, 256>>>(query, Wq, bq, nullptr, 0);
    mha_proj_mma<<<gproj, 256>>>(key_,  Wk, bk, nullptr, 1);
    mha_proj_mma<<<gproj, 256>>>(value, Wv, bv, nullptr, 2);

    dim3 gsc(Sdim/128, Sdim/128, Bdim*Hdim);        // (16,16,32)
    mha_scores_mma<<<gsc, 256>>>(bias_matrix, attn);

    mha_softmax_kernel<<<Bdim*Hdim*Sdim, 256>>>(attn);

    dim3 gctx(Sdim/128, Bdim*Hdim);                 // (16,32)
    mha_ctx_mma<<<gctx, 256>>>(attn);

    mha_proj_mma<<<gproj, 256>>>(nullptr, Wo, bo, out, 3);
}